// round 8
// baseline (speedup 1.0000x reference)
#include <cuda_runtime.h>
#include <cuda_bf16.h>

// BBAStar: 8-connected grid shortest path, B=128, 32x32.
// R7: concurrent dual-orientation GS on SEPARATE arrays + per-epoch merge.
//   warps 0-7  : V bands (4 rows each, lane=col) sweep distV
//   warps 8-15 : H bands (4 cols each, lane=row) sweep distH
// Single owner per array => plain stores, full GS freshness, no atomics.
// Epoch: sweeps (concurrent) -> barrier -> elementwise fminf merge written to
// both arrays -> __syncthreads_or(change). Merged values are monotone valid
// upper bounds >= d*; a zero-change epoch means both (equal) arrays are fixed
// points of the full 8-neighbor operator => result is the bit-exact float
// fixed point of the reference's 1024 Jacobi sweeps (sandwich argument).
// Backtrack via precomputed argmin directions (OFFS first-occurrence tie-break).

#define BN 128
#define ST 35              // smem row stride (odd => conflict-free both axes)
#define INF_F 1000000000.0f
#define EPS_F 1e-6f
#define KP 2               // fwd+bwd sweep pairs per epoch

__device__ __forceinline__ float shl(float v, int lane) {
    float t = __shfl_up_sync(0xffffffffu, v, 1);
    return (lane == 0) ? INF_F : t;
}
__device__ __forceinline__ float shr(float v, int lane) {
    float t = __shfl_down_sync(0xffffffffu, v, 1);
    return (lane == 31) ? INF_F : t;
}
__device__ __forceinline__ float min8f(float a, float b, float c, float d,
                                       float e, float f, float g, float h) {
    return fminf(fminf(fminf(a, b), fminf(c, d)),
                 fminf(fminf(e, f), fminf(g, h)));
}
__device__ __forceinline__ int pick8(float a0, float a1, float a2, float a3,
                                     float a4, float a5, float a6, float a7) {
    float bb = a0; int bd = 0;
    if (a1 < bb) { bb = a1; bd = 1; }
    if (a2 < bb) { bb = a2; bd = 2; }
    if (a3 < bb) { bb = a3; bd = 3; }
    if (a4 < bb) { bb = a4; bd = 4; }
    if (a5 < bb) { bb = a5; bd = 5; }
    if (a6 < bb) { bb = a6; bd = 6; }
    if (a7 < bb) { bb = a7; bd = 7; }
    return bd;
}

// Forward GS sweep over the 4 owned lines (fresh prev-line shfls; current-line
// shfls reused from the previous line's next-line shfls).
__device__ __forceinline__ void sweep_fwd(volatile float* vd, const float w[4],
                                          float d[4], int i0, int di,
                                          int ix, int iy, int lane, bool& any)
{
    float X = vd[ix], Y = vd[iy];
    float p = X, pl = shl(X, lane), pr = shr(X, lane);
    float cl = shl(d[0], lane), cr = shr(d[0], lane);
    #pragma unroll
    for (int i = 0; i < 4; ++i) {
        float nx = (i < 3) ? d[i + 1] : Y;
        float nl = shl(nx, lane), nr = shr(nx, lane);
        float v = w[i] + min8f(pl, p, pr, cl, cr, nl, nx, nr);
        if (v < d[i]) { d[i] = v; vd[i0 + i * di] = v; any = true; }
        p = d[i]; pl = shl(p, lane); pr = shr(p, lane);
        cl = nl; cr = nr;
    }
}
__device__ __forceinline__ void sweep_bwd(volatile float* vd, const float w[4],
                                          float d[4], int i0, int di,
                                          int ix, int iy, int lane, bool& any)
{
    float X = vd[ix], Y = vd[iy];
    float p = Y, pl = shl(Y, lane), pr = shr(Y, lane);
    float cl = shl(d[3], lane), cr = shr(d[3], lane);
    #pragma unroll
    for (int i = 3; i >= 0; --i) {
        float nx = (i > 0) ? d[i - 1] : X;
        float nl = shl(nx, lane), nr = shr(nx, lane);
        float v = w[i] + min8f(nl, nx, nr, cl, cr, pl, p, pr);
        if (v < d[i]) { d[i] = v; vd[i0 + i * di] = v; any = true; }
        p = d[i]; pl = shl(p, lane); pr = shr(p, lane);
        cl = nl; cr = nr;
    }
}

__global__ void __launch_bounds__(512, 1)
bba_kernel(const float* __restrict__ weights,
           const int*   __restrict__ source,
           const int*   __restrict__ target,
           float*       __restrict__ out)
{
    __shared__ float dV[34 * ST];       // padded 34x34, stride 35
    __shared__ float dH[34 * ST];
    __shared__ float wsh[32][33];       // weights, conflict-free both axes
    __shared__ int   nbr[1024];

    const int b    = blockIdx.x;
    const int tid  = threadIdx.x;
    const int wpid = tid >> 5;          // 0..15
    const int lane = tid & 31;
    const bool isV = (wpid < 8);
    const int g0   = 4 * (wpid & 7);    // band start (row for V, col for H)

    // Weights first (DRAM latency), linear coalesced.
    const float* wb = weights + b * 1024;
    float wtmp[2];
    #pragma unroll
    for (int i = 0; i < 2; ++i) wtmp[i] = wb[i * 512 + tid] + EPS_F;

    const int sr = source[2 * b + 0];
    const int sc = source[2 * b + 1];
    const int tr = target[2 * b + 0];
    const int tc = target[2 * b + 1];

    // Zero poisoned output slice.
    out[b * 1024 + tid]       = 0.0f;
    out[b * 1024 + 512 + tid] = 0.0f;

    for (int i = tid; i < 34 * ST; i += 512) { dV[i] = INF_F; dH[i] = INF_F; }
    #pragma unroll
    for (int i = 0; i < 2; ++i) {
        int idx = i * 512 + tid;
        wsh[idx >> 5][idx & 31] = wtmp[i];
    }
    __syncthreads();

    // Per-warp band weights.
    float wreg[4];
    #pragma unroll
    for (int i = 0; i < 4; ++i)
        wreg[i] = isV ? wsh[g0 + i][lane] : wsh[lane][g0 + i];

    if (tid == 0) {
        float s = wsh[sr][sc];
        dV[(sr + 1) * ST + (sc + 1)] = s;
        dH[(sr + 1) * ST + (sc + 1)] = s;
    }
    __syncthreads();

    // Own-array, own-orientation indices.
    volatile float* arr = isV ? (volatile float*)dV : (volatile float*)dH;
    const int di = isV ? ST : 1;
    const int i0 = isV ? ((g0 + 1) * ST + (lane + 1))
                       : ((lane + 1) * ST + (g0 + 1));
    const int ix = isV ? ((g0 + 0) * ST + (lane + 1))
                       : ((lane + 1) * ST + (g0 + 0));
    const int iy = isV ? ((g0 + 5) * ST + (lane + 1))
                       : ((lane + 1) * ST + (g0 + 5));

    float d[4];

    for (;;) {
        bool any = false;

        // Concurrent sweeps: V warps on dV, H warps on dH.
        #pragma unroll
        for (int i = 0; i < 4; ++i) d[i] = arr[i0 + i * di];
        #pragma unroll 1
        for (int k = 0; k < KP; ++k) {
            sweep_fwd(arr, wreg, d, i0, di, ix, iy, lane, any);
            sweep_bwd(arr, wreg, d, i0, di, ix, iy, lane, any);
        }

        __syncthreads();                 // sweeps done before merge

        // Merge: both arrays <- elementwise min (2 interior cells per thread).
        #pragma unroll
        for (int i = 0; i < 2; ++i) {
            int idx = i * 512 + tid;
            int off = ((idx >> 5) + 1) * ST + (idx & 31) + 1;
            float m = fminf(dV[off], dH[off]);
            dV[off] = m; dH[off] = m;
        }

        if (!__syncthreads_or((int)any)) break;  // zero-change epoch => d*
    }

    // Parallel argmin-neighbor directions from dV (== d*), V warps, OFFS order:
    // (-1,-1),(-1,0),(-1,1),(0,-1),(0,1),(1,-1),(1,0),(1,1)
    if (isV) {
        #pragma unroll
        for (int i = 0; i < 4; ++i) d[i] = dV[i0 + i * ST];
        float X  = dV[ix], Y = dV[iy];
        float XL = shl(X, lane),    XR = shr(X, lane);
        float L0 = shl(d[0], lane), R0 = shr(d[0], lane);
        float L1 = shl(d[1], lane), R1 = shr(d[1], lane);
        float L2 = shl(d[2], lane), R2 = shr(d[2], lane);
        float L3 = shl(d[3], lane), R3 = shr(d[3], lane);
        float YL = shl(Y, lane),    YR = shr(Y, lane);
        nbr[(g0 + 0) * 32 + lane] = pick8(XL, X,    XR, L0, R0, L1, d[1], R1);
        nbr[(g0 + 1) * 32 + lane] = pick8(L0, d[0], R0, L1, R1, L2, d[2], R2);
        nbr[(g0 + 2) * 32 + lane] = pick8(L1, d[1], R1, L2, R2, L3, d[3], R3);
        nbr[(g0 + 3) * 32 + lane] = pick8(L2, d[2], R2, L3, R3, YL, Y,    YR);
    }
    __syncthreads();

    // Serial backtrack: follow precomputed directions.
    if (tid == 0) {
        const int drs[8] = {-1, -1, -1,  0, 0,  1, 1, 1};
        const int dcs[8] = {-1,  0,  1, -1, 1, -1, 0, 1};
        int cr = tr, cc = tc;
        float* o = out + b * 1024;
        for (int step = 0; step < 1024; ++step) {
            o[cr * 32 + cc] = 1.0f;
            if (cr == sr && cc == sc) break;
            int k = nbr[cr * 32 + cc];
            cr += drs[k];
            cc += dcs[k];
        }
    }
}

extern "C" void kernel_launch(void* const* d_in, const int* in_sizes, int n_in,
                              void* d_out, int out_size)
{
    const float* weights = (const float*)d_in[0];
    const int*   source  = (const int*)d_in[1];
    const int*   target  = (const int*)d_in[2];
    float*       out     = (float*)d_out;

    bba_kernel<<<BN, 512>>>(weights, source, target, out);
}